// round 5
// baseline (speedup 1.0000x reference)
#include <cuda_runtime.h>
#include <cuda_bf16.h>
#include <cstdint>
#include <cstddef>

#define DINL __device__ __forceinline__

// ---------------- problem constants ----------------
constexpr int C = 512;           // feature dim
constexpr int P = 512;           // prototypes
constexpr int N_MAX = 65536;     // instances
constexpr int TILE_M = 128;      // instances per CTA (pass1)
constexpr int TILE_P = 256;      // protos per CTA (pass1)
constexpr int KC = 64;           // K chunk
constexpr int NCHUNKS = C / KC;  // 8
constexpr int SKB = 144;         // padded smem row stride in BYTES (64 bf16 + 8 pad)
constexpr int MAX_BLOCKS = 1024;
constexpr int TPAD = 68;         // staging tile row stride (floats): 64 + 4 pad

// ---------------- device scratch (static — no allocations) ----------------
__device__ __align__(16) __nv_bfloat16 g_proto_bf[P * C];
__device__ __align__(16) __nv_bfloat16 g_xbf[(size_t)N_MAX * C];
__device__ float g_psq[P];
__device__ float g_xsq[N_MAX];
__device__ float g_partial[(size_t)P * MAX_BLOCKS];
__device__ float g_rcp[P];

// ---------------- PTX helpers ----------------
DINL uint32_t smem_u32(const void* p) {
    uint32_t r;
    asm("{ .reg .u64 t; cvta.to.shared.u64 t, %1; cvt.u32.u64 %0, t; }"
        : "=r"(r) : "l"(p));
    return r;
}

#define CP_ASYNC16(dst, src) \
    asm volatile("cp.async.cg.shared.global [%0], [%1], 16;" \
                 :: "r"(dst), "l"(src) : "memory")
#define CP_COMMIT() asm volatile("cp.async.commit_group;" ::: "memory")
#define CP_WAIT(n)  asm volatile("cp.async.wait_group %0;" :: "n"(n) : "memory")

#define LDSM_X4(r0, r1, r2, r3, addr) \
    asm volatile("ldmatrix.sync.aligned.m8n8.x4.shared.b16 {%0,%1,%2,%3}, [%4];" \
                 : "=r"(r0), "=r"(r1), "=r"(r2), "=r"(r3) : "r"(addr))
#define LDSM_X2(r0, r1, addr) \
    asm volatile("ldmatrix.sync.aligned.m8n8.x2.shared.b16 {%0,%1}, [%2];" \
                 : "=r"(r0), "=r"(r1) : "r"(addr))

#define MMA_BF16(c, a, b0, b1) \
    asm volatile("mma.sync.aligned.m16n8k16.row.col.f32.bf16.bf16.f32 " \
                 "{%0,%1,%2,%3}, {%4,%5,%6,%7}, {%8,%9}, {%0,%1,%2,%3};" \
                 : "+f"((c)[0]), "+f"((c)[1]), "+f"((c)[2]), "+f"((c)[3]) \
                 : "r"((a)[0]), "r"((a)[1]), "r"((a)[2]), "r"((a)[3]), \
                   "r"(b0), "r"(b1))

DINL uint32_t bf2_bits(__nv_bfloat162 v) { return *reinterpret_cast<uint32_t*>(&v); }

// ---------------- pass1 SMEM layout (bytes) ----------------
constexpr uint32_t SM_XSQ  = 0;                            // 128 f
constexpr uint32_t SM_PSQ  = 512;                          // 256 f
constexpr uint32_t SM_SUMS = 1536;                         // 256 f
constexpr uint32_t SM_A0   = 4096;                         // 128 x 144B
constexpr uint32_t SM_A1   = SM_A0 + TILE_M * SKB;         // 22528
constexpr uint32_t SM_B0   = SM_A1 + TILE_M * SKB;         // 40960: 256 x 144B
constexpr uint32_t SM_B1   = SM_B0 + TILE_P * SKB;         // 77824
constexpr uint32_t SMEM1_BYTES = SM_B1 + TILE_P * SKB;     // 114688
// epilogue staging tile reuses [SM_A0, ...): 256 x 68 floats = 69632 B
constexpr uint32_t SM_TILE = SM_A0;

// ============================================================
// prep: proto fp32 -> bf16 + ||p||^2
// ============================================================
__global__ void prep_kernel(const float* __restrict__ proto) {
    const int p = blockIdx.x;
    const int t = threadIdx.x;  // 128 threads
    float4 v = ((const float4*)(proto + (size_t)p * C))[t];
    __nv_bfloat162 b0 = __float22bfloat162_rn(make_float2(v.x, v.y));
    __nv_bfloat162 b1 = __float22bfloat162_rn(make_float2(v.z, v.w));
    *(uint2*)(g_proto_bf + (size_t)p * C + t * 4) = make_uint2(bf2_bits(b0), bf2_bits(b1));
    float sq = v.x * v.x + v.y * v.y + v.z * v.z + v.w * v.w;
    #pragma unroll
    for (int m = 1; m < 32; m <<= 1) sq += __shfl_xor_sync(0xffffffffu, sq, m);
    __shared__ float ws[4];
    if ((t & 31) == 0) ws[t >> 5] = sq;
    __syncthreads();
    if (t == 0) g_psq[p] = ws[0] + ws[1] + ws[2] + ws[3];
}

// ============================================================
// convert: x fp32 -> bf16 + ||x||^2 per instance
// ============================================================
__global__ void convert_kernel(const float* __restrict__ x) {
    const int row = blockIdx.x;
    const int t = threadIdx.x;  // 128 threads
    float4 v = ((const float4*)(x + (size_t)row * C))[t];
    __nv_bfloat162 b0 = __float22bfloat162_rn(make_float2(v.x, v.y));
    __nv_bfloat162 b1 = __float22bfloat162_rn(make_float2(v.z, v.w));
    *(uint2*)(g_xbf + (size_t)row * C + t * 4) = make_uint2(bf2_bits(b0), bf2_bits(b1));
    float sq = v.x * v.x + v.y * v.y + v.z * v.z + v.w * v.w;
    #pragma unroll
    for (int m = 1; m < 32; m <<= 1) sq += __shfl_xor_sync(0xffffffffu, sq, m);
    __shared__ float ws[4];
    if ((t & 31) == 0) ws[t >> 5] = sq;
    __syncthreads();
    if (t == 0) g_xsq[row] = ws[0] + ws[1] + ws[2] + ws[3];
}

// ============================================================
// pass1: bf16 mma.sync GEMM tile (128 inst x 256 protos, K=512)
//        -> s = rsqrt(d2) into weights plane (coalesced via smem staging)
//        + per-CTA column sums
// ============================================================
__global__ __launch_bounds__(256, 1)
void pass1_kernel(float* __restrict__ w_s, int Ninst) {
    extern __shared__ char smem[];
    const uint32_t sb = smem_u32(smem);
    const int tid  = threadIdx.x;
    const int wid  = tid >> 5;
    const int l    = tid & 31;
    const int mw   = wid >> 2;   // 0..1 : instance-half of tile
    const int nw   = wid & 3;    // 0..3 : proto-quarter of tile
    const int n0   = blockIdx.x * TILE_M;
    const int p0   = blockIdx.y * TILE_P;

    // stage xsq / psq
    if (tid < 128) ((float*)(smem + SM_XSQ))[tid] = g_xsq[n0 + tid];
    ((float*)(smem + SM_PSQ))[tid] = g_psq[p0 + tid];

    // per-thread cp.async source/dest bases
    const __nv_bfloat16* aSrc = g_xbf + (size_t)(n0 + (tid >> 1)) * C + (tid & 1) * 32;
    const __nv_bfloat16* bSrc = g_proto_bf + (size_t)(p0 + tid) * C;
    const uint32_t aDst0 = sb + SM_A0 + (tid >> 1) * SKB + (tid & 1) * 64;
    const uint32_t bDst0 = sb + SM_B0 + tid * SKB;
    const uint32_t bufStrideA = SM_A1 - SM_A0;
    const uint32_t bufStrideB = SM_B1 - SM_B0;

    #define ISSUE_CHUNK(ck, buf) do {                                          \
        const uint32_t _ad = aDst0 + (buf) * bufStrideA;                        \
        const uint32_t _bd = bDst0 + (buf) * bufStrideB;                        \
        const __nv_bfloat16* _as = aSrc + (ck) * KC;                            \
        const __nv_bfloat16* _bs = bSrc + (ck) * KC;                            \
        _Pragma("unroll")                                                       \
        for (int j = 0; j < 4; j++) CP_ASYNC16(_ad + j * 16, _as + j * 8);      \
        _Pragma("unroll")                                                       \
        for (int j = 0; j < 8; j++) CP_ASYNC16(_bd + j * 16, _bs + j * 8);      \
        CP_COMMIT();                                                            \
    } while (0)

    ISSUE_CHUNK(0, 0);
    ISSUE_CHUNK(1, 1);

    // fragment lane offsets
    const uint32_t aRowOff = (mw * 64 + (l & 15)) * SKB + (l >> 4) * 16;
    const uint32_t bRowOff = (nw * 64 + (l & 7)) * SKB + ((l >> 3) & 1) * 16;

    float c[4][8][4];
    #pragma unroll
    for (int im = 0; im < 4; im++)
        #pragma unroll
        for (int in = 0; in < 8; in++)
            #pragma unroll
            for (int r = 0; r < 4; r++) c[im][in][r] = 0.f;

    #pragma unroll 1
    for (int ck = 0; ck < NCHUNKS; ck++) {
        if (ck >= NCHUNKS - 2) { CP_WAIT(0); } else { CP_WAIT(1); }
        __syncthreads();
        const int buf = ck & 1;
        const uint32_t Ab = sb + (buf ? SM_A1 : SM_A0) + aRowOff;
        const uint32_t Bb = sb + (buf ? SM_B1 : SM_B0) + bRowOff;
        #pragma unroll
        for (int ks = 0; ks < 4; ks++) {
            uint32_t a[4][4];
            #pragma unroll
            for (int im = 0; im < 4; im++)
                LDSM_X4(a[im][0], a[im][1], a[im][2], a[im][3],
                        Ab + im * 16 * SKB + ks * 32);
            #pragma unroll
            for (int in = 0; in < 8; in++) {
                uint32_t b0, b1;
                LDSM_X2(b0, b1, Bb + in * 8 * SKB + ks * 32);
                #pragma unroll
                for (int im = 0; im < 4; im++)
                    MMA_BF16(c[im][in], a[im], b0, b1);
            }
        }
        __syncthreads();
        if (ck + 2 < NCHUNKS) ISSUE_CHUNK(ck + 2, buf);
    }

    // ---------------- epilogue: transform + smem-staged coalesced stores ----
    const float* xsq_s = (const float*)(smem + SM_XSQ);
    const float* psq_s = (const float*)(smem + SM_PSQ);
    float* sums = (float*)(smem + SM_SUMS);   // [256] per-proto partials
    float* tile = (float*)(smem + SM_TILE);   // [256][TPAD]

    #pragma unroll 1
    for (int r = 0; r < 2; r++) {
        __syncthreads();  // staging tile free (mainloop buffers / prev round done)
        if (mw == r) {
            #pragma unroll
            for (int im = 0; im < 4; im++) {
                #pragma unroll
                for (int rh = 0; rh < 2; rh++) {
                    const int rowl = im * 16 + (l >> 2) + rh * 8;   // 0..63
                    const float xq = xsq_s[r * 64 + rowl];
                    #pragma unroll
                    for (int in = 0; in < 8; in++) {
                        const int plb = nw * 64 + in * 8 + (l & 3) * 2;
                        #pragma unroll
                        for (int cj = 0; cj < 2; cj++) {
                            const float acc = c[im][in][rh * 2 + cj];
                            float d2 = fmaxf(fmaf(-2.f, acc, psq_s[plb + cj] + xq), 1e-20f);
                            tile[(plb + cj) * TPAD + rowl] = rsqrtf(d2);
                        }
                    }
                }
            }
        }
        __syncthreads();
        // all 8 warps: warp wid stores protos wid*32 .. wid*32+31 (64 inst each)
        #pragma unroll 4
        for (int pp = 0; pp < 32; pp++) {
            const int p = wid * 32 + pp;
            float2 v = *(const float2*)(tile + p * TPAD + l * 2);
            *(float2*)(w_s + (size_t)(p0 + p) * Ninst + n0 + r * 64 + l * 2) = v;
            float t = v.x + v.y;
            #pragma unroll
            for (int m = 1; m < 32; m <<= 1) t += __shfl_xor_sync(0xffffffffu, t, m);
            if (l == 0) {
                if (r == 0) sums[p] = t; else sums[p] += t;
            }
        }
    }
    __syncthreads();
    {
        g_partial[(size_t)(p0 + tid) * gridDim.x + blockIdx.x] = sums[tid];
    }
}

// ============================================================
// reduce: fixed-order tree over per-CTA partials -> g_rcp[p] = 1/sum
// ============================================================
__global__ void reduce_kernel(int nblk) {
    const int p = blockIdx.x;
    float s = 0.f;
    for (int i = threadIdx.x; i < nblk; i += 256)
        s += g_partial[(size_t)p * nblk + i];
    #pragma unroll
    for (int m = 1; m < 32; m <<= 1) s += __shfl_xor_sync(0xffffffffu, s, m);
    __shared__ float ws[8];
    if ((threadIdx.x & 31) == 0) ws[threadIdx.x >> 5] = s;
    __syncthreads();
    if (threadIdx.x == 0) {
        float t = 0.f;
        #pragma unroll
        for (int i = 0; i < 8; i++) t += ws[i];
        g_rcp[p] = 1.0f / t;
    }
}

// ============================================================
// pass2: scale s -> weights (in place), transpose via smem, x_out = w^T * x
// ============================================================
__global__ __launch_bounds__(256)
void pass2_kernel(const float* __restrict__ x, float* __restrict__ w,
                  float* __restrict__ x_out, int Ninst) {
    extern __shared__ float tile[];  // [128][129]
    const int n0 = blockIdx.x * 128;
    const int p0 = blockIdx.y * 128;
    const int tx = threadIdx.x & 31, ty = threadIdx.x >> 5;

    #pragma unroll
    for (int i = 0; i < 16; i++) {
        const int pl = i * 8 + ty;
        const float r = g_rcp[p0 + pl];
        float4* wp = (float4*)(w + (size_t)(p0 + pl) * Ninst + n0) + tx;
        float4 v = *wp;
        v.x *= r; v.y *= r; v.z *= r; v.w *= r;
        *wp = v;
        float* t = tile + pl * 129 + tx * 4;
        t[0] = v.x; t[1] = v.y; t[2] = v.z; t[3] = v.w;
    }
    __syncthreads();
    #pragma unroll
    for (int pp = 0; pp < 4; pp++) {
        const int pl = pp * 32 + tx;
        #pragma unroll
        for (int i = 0; i < 16; i++) {
            const int nl = i * 8 + ty;
            const size_t idx = (size_t)(n0 + nl) * C + p0 + pl;
            x_out[idx] = x[idx] * tile[pl * 129 + nl];
        }
    }
}

// ============================================================
// launch
// ============================================================
extern "C" void kernel_launch(void* const* d_in, const int* in_sizes, int n_in,
                              void* d_out, int out_size) {
    const float* x     = (const float*)d_in[0];
    const float* proto = (const float*)d_in[1];
    const int Ninst = in_sizes[0] / C;            // 65536
    float* x_out   = (float*)d_out;               // (N, C)
    float* weights = x_out + (size_t)Ninst * C;   // (P, N)
    const int nblk = Ninst / TILE_M;              // 512

    cudaFuncSetAttribute(pass1_kernel, cudaFuncAttributeMaxDynamicSharedMemorySize,
                         (int)SMEM1_BYTES);
    cudaFuncSetAttribute(pass2_kernel, cudaFuncAttributeMaxDynamicSharedMemorySize,
                         128 * 129 * 4);

    prep_kernel<<<P, 128>>>(proto);
    convert_kernel<<<Ninst, 128>>>(x);
    pass1_kernel<<<dim3(nblk, P / TILE_P), 256, SMEM1_BYTES>>>(weights, Ninst);
    reduce_kernel<<<P, 256>>>(nblk);
    pass2_kernel<<<dim3(Ninst / 128, P / 128), 256, 128 * 129 * 4>>>(x, weights, x_out, Ninst);
}

// round 6
// speedup vs baseline: 1.1298x; 1.1298x over previous
#include <cuda_runtime.h>
#include <cuda_bf16.h>
#include <cstdint>
#include <cstddef>

#define DINL __device__ __forceinline__

// ---------------- problem constants ----------------
constexpr int C = 512;           // feature dim
constexpr int P = 512;           // prototypes
constexpr int N_MAX = 65536;     // instances
constexpr int TILE_M = 128;      // instances per CTA (pass1)
constexpr int TILE_P = 256;      // protos per CTA (pass1)
constexpr int KC = 64;           // K chunk
constexpr int NCHUNKS = C / KC;  // 8
constexpr int SKB = 144;         // padded smem row stride in BYTES (64 bf16 + 8 pad)
constexpr int MAX_BLOCKS = 1024;

// ---------------- device scratch (static — no allocations) ----------------
__device__ __align__(16) __nv_bfloat16 g_proto_bf[P * C];
__device__ __align__(16) __nv_bfloat16 g_xbf[(size_t)N_MAX * C];
__device__ float g_psq[P];
__device__ float g_xsq[N_MAX];
__device__ float g_partial[(size_t)P * MAX_BLOCKS];
__device__ float g_rcp[P];

// ---------------- PTX helpers ----------------
DINL uint32_t smem_u32(const void* p) {
    uint32_t r;
    asm("{ .reg .u64 t; cvta.to.shared.u64 t, %1; cvt.u32.u64 %0, t; }"
        : "=r"(r) : "l"(p));
    return r;
}

#define CP_ASYNC16(dst, src) \
    asm volatile("cp.async.cg.shared.global [%0], [%1], 16;" \
                 :: "r"(dst), "l"(src) : "memory")
#define CP_COMMIT() asm volatile("cp.async.commit_group;" ::: "memory")
#define CP_WAIT(n)  asm volatile("cp.async.wait_group %0;" :: "n"(n) : "memory")

#define LDSM_X4(r0, r1, r2, r3, addr) \
    asm volatile("ldmatrix.sync.aligned.m8n8.x4.shared.b16 {%0,%1,%2,%3}, [%4];" \
                 : "=r"(r0), "=r"(r1), "=r"(r2), "=r"(r3) : "r"(addr))
#define LDSM_X2(r0, r1, addr) \
    asm volatile("ldmatrix.sync.aligned.m8n8.x2.shared.b16 {%0,%1}, [%2];" \
                 : "=r"(r0), "=r"(r1) : "r"(addr))

#define MMA_BF16(c, a, b0, b1) \
    asm volatile("mma.sync.aligned.m16n8k16.row.col.f32.bf16.bf16.f32 " \
                 "{%0,%1,%2,%3}, {%4,%5,%6,%7}, {%8,%9}, {%0,%1,%2,%3};" \
                 : "+f"((c)[0]), "+f"((c)[1]), "+f"((c)[2]), "+f"((c)[3]) \
                 : "r"((a)[0]), "r"((a)[1]), "r"((a)[2]), "r"((a)[3]), \
                   "r"(b0), "r"(b1))

DINL uint32_t bf2_bits(__nv_bfloat162 v) { return *reinterpret_cast<uint32_t*>(&v); }

// ---------------- pass1 SMEM layout (bytes) ----------------
constexpr uint32_t SM_XSQ  = 0;                            // 128 f
constexpr uint32_t SM_PSQ  = 512;                          // 256 f
constexpr uint32_t SM_SUMS = 1536;                         // 2 x 256 f
constexpr uint32_t SM_A0   = 4096;                         // 128 x 144B
constexpr uint32_t SM_A1   = SM_A0 + TILE_M * SKB;         // 22528
constexpr uint32_t SM_B0   = SM_A1 + TILE_M * SKB;         // 40960: 256 x 144B
constexpr uint32_t SM_B1   = SM_B0 + TILE_P * SKB;         // 77824
constexpr uint32_t SMEM1_BYTES = SM_B1 + TILE_P * SKB;     // 114688

// ============================================================
// prep: proto fp32 -> bf16 + ||p||^2
// ============================================================
__global__ void prep_kernel(const float* __restrict__ proto) {
    const int p = blockIdx.x;
    const int t = threadIdx.x;  // 128 threads
    float4 v = ((const float4*)(proto + (size_t)p * C))[t];
    __nv_bfloat162 b0 = __float22bfloat162_rn(make_float2(v.x, v.y));
    __nv_bfloat162 b1 = __float22bfloat162_rn(make_float2(v.z, v.w));
    *(uint2*)(g_proto_bf + (size_t)p * C + t * 4) = make_uint2(bf2_bits(b0), bf2_bits(b1));
    float sq = v.x * v.x + v.y * v.y + v.z * v.z + v.w * v.w;
    #pragma unroll
    for (int m = 1; m < 32; m <<= 1) sq += __shfl_xor_sync(0xffffffffu, sq, m);
    __shared__ float ws[4];
    if ((t & 31) == 0) ws[t >> 5] = sq;
    __syncthreads();
    if (t == 0) g_psq[p] = ws[0] + ws[1] + ws[2] + ws[3];
}

// ============================================================
// convert: x fp32 -> bf16 + ||x||^2 per instance
// ============================================================
__global__ void convert_kernel(const float* __restrict__ x) {
    const int row = blockIdx.x;
    const int t = threadIdx.x;  // 128 threads
    float4 v = ((const float4*)(x + (size_t)row * C))[t];
    __nv_bfloat162 b0 = __float22bfloat162_rn(make_float2(v.x, v.y));
    __nv_bfloat162 b1 = __float22bfloat162_rn(make_float2(v.z, v.w));
    *(uint2*)(g_xbf + (size_t)row * C + t * 4) = make_uint2(bf2_bits(b0), bf2_bits(b1));
    float sq = v.x * v.x + v.y * v.y + v.z * v.z + v.w * v.w;
    #pragma unroll
    for (int m = 1; m < 32; m <<= 1) sq += __shfl_xor_sync(0xffffffffu, sq, m);
    __shared__ float ws[4];
    if ((t & 31) == 0) ws[t >> 5] = sq;
    __syncthreads();
    if (t == 0) g_xsq[row] = ws[0] + ws[1] + ws[2] + ws[3];
}

// ============================================================
// dummy: shifts the ncu capture slot so pass1 lands on it
// ============================================================
__global__ void dummy_kernel() {}

// ============================================================
// pass1: bf16 mma.sync GEMM tile (128 inst x 256 protos, K=512)
//        -> s = rsqrt(d2) into weights plane + per-CTA column sums
// ============================================================
__global__ __launch_bounds__(256, 1)
void pass1_kernel(float* __restrict__ w_s, int Ninst) {
    extern __shared__ char smem[];
    const uint32_t sb = smem_u32(smem);
    const int tid  = threadIdx.x;
    const int wid  = tid >> 5;
    const int l    = tid & 31;
    const int mw   = wid >> 2;   // 0..1 : instance-half of tile
    const int nw   = wid & 3;    // 0..3 : proto-quarter of tile
    const int n0   = blockIdx.x * TILE_M;
    const int p0   = blockIdx.y * TILE_P;

    // stage xsq / psq
    if (tid < 128) ((float*)(smem + SM_XSQ))[tid] = g_xsq[n0 + tid];
    ((float*)(smem + SM_PSQ))[tid] = g_psq[p0 + tid];

    // per-thread cp.async source/dest bases
    const __nv_bfloat16* aSrc = g_xbf + (size_t)(n0 + (tid >> 1)) * C + (tid & 1) * 32;
    const __nv_bfloat16* bSrc = g_proto_bf + (size_t)(p0 + tid) * C;
    const uint32_t aDst0 = sb + SM_A0 + (tid >> 1) * SKB + (tid & 1) * 64;
    const uint32_t bDst0 = sb + SM_B0 + tid * SKB;
    const uint32_t bufStrideA = SM_A1 - SM_A0;
    const uint32_t bufStrideB = SM_B1 - SM_B0;

    #define ISSUE_CHUNK(ck, buf) do {                                          \
        const uint32_t _ad = aDst0 + (buf) * bufStrideA;                        \
        const uint32_t _bd = bDst0 + (buf) * bufStrideB;                        \
        const __nv_bfloat16* _as = aSrc + (ck) * KC;                            \
        const __nv_bfloat16* _bs = bSrc + (ck) * KC;                            \
        _Pragma("unroll")                                                       \
        for (int j = 0; j < 4; j++) CP_ASYNC16(_ad + j * 16, _as + j * 8);      \
        _Pragma("unroll")                                                       \
        for (int j = 0; j < 8; j++) CP_ASYNC16(_bd + j * 16, _bs + j * 8);      \
        CP_COMMIT();                                                            \
    } while (0)

    ISSUE_CHUNK(0, 0);
    ISSUE_CHUNK(1, 1);

    // fragment lane offsets
    const uint32_t aRowOff = (mw * 64 + (l & 15)) * SKB + (l >> 4) * 16;
    const uint32_t bRowOff = (nw * 64 + (l & 7)) * SKB + ((l >> 3) & 1) * 16;

    float c[4][8][4];
    #pragma unroll
    for (int im = 0; im < 4; im++)
        #pragma unroll
        for (int in = 0; in < 8; in++)
            #pragma unroll
            for (int r = 0; r < 4; r++) c[im][in][r] = 0.f;

    #pragma unroll 1
    for (int ck = 0; ck < NCHUNKS; ck++) {
        if (ck >= NCHUNKS - 2) { CP_WAIT(0); } else { CP_WAIT(1); }
        __syncthreads();
        const int buf = ck & 1;
        const uint32_t Ab = sb + (buf ? SM_A1 : SM_A0) + aRowOff;
        const uint32_t Bb = sb + (buf ? SM_B1 : SM_B0) + bRowOff;
        #pragma unroll
        for (int ks = 0; ks < 4; ks++) {
            uint32_t a[4][4];
            #pragma unroll
            for (int im = 0; im < 4; im++)
                LDSM_X4(a[im][0], a[im][1], a[im][2], a[im][3],
                        Ab + im * 16 * SKB + ks * 32);
            #pragma unroll
            for (int in = 0; in < 8; in++) {
                uint32_t b0, b1;
                LDSM_X2(b0, b1, Bb + in * 8 * SKB + ks * 32);
                #pragma unroll
                for (int im = 0; im < 4; im++)
                    MMA_BF16(c[im][in], a[im], b0, b1);
            }
        }
        __syncthreads();
        if (ck + 2 < NCHUNKS) ISSUE_CHUNK(ck + 2, buf);
    }

    // ---------------- epilogue (direct stores: 4 full 32B sectors / warp op) --
    const float* xsq_s = (const float*)(smem + SM_XSQ);
    const float* psq_s = (const float*)(smem + SM_PSQ);
    float* sums = (float*)(smem + SM_SUMS);

    float csum[8][2];
    #pragma unroll
    for (int in = 0; in < 8; in++) { csum[in][0] = 0.f; csum[in][1] = 0.f; }

    #pragma unroll
    for (int im = 0; im < 4; im++) {
        const int rbase = mw * 64 + im * 16 + (l >> 2);
        #pragma unroll
        for (int rh = 0; rh < 2; rh++) {
            const int row = rbase + rh * 8;
            const float xq = xsq_s[row];
            const size_t gcol = (size_t)(n0 + row);
            #pragma unroll
            for (int in = 0; in < 8; in++) {
                const int pl = nw * 64 + in * 8 + (l & 3) * 2;
                #pragma unroll
                for (int cj = 0; cj < 2; cj++) {
                    const float acc = c[im][in][rh * 2 + cj];
                    float d2 = fmaxf(fmaf(-2.f, acc, psq_s[pl + cj] + xq), 1e-20f);
                    float s = rsqrtf(d2);
                    w_s[(size_t)(p0 + pl + cj) * Ninst + gcol] = s;
                    csum[in][cj] += s;
                }
            }
        }
    }
    // reduce column sums over lanes sharing (l&3)
    #pragma unroll
    for (int in = 0; in < 8; in++) {
        #pragma unroll
        for (int cj = 0; cj < 2; cj++) {
            float v = csum[in][cj];
            v += __shfl_xor_sync(0xffffffffu, v, 4);
            v += __shfl_xor_sync(0xffffffffu, v, 8);
            v += __shfl_xor_sync(0xffffffffu, v, 16);
            if (l < 4) sums[mw * 256 + nw * 64 + in * 8 + l * 2 + cj] = v;
        }
    }
    __syncthreads();
    {
        float tot = sums[tid] + sums[256 + tid];
        g_partial[(size_t)(p0 + tid) * gridDim.x + blockIdx.x] = tot;
    }
}

// ============================================================
// reduce: fixed-order tree over per-CTA partials -> g_rcp[p] = 1/sum
// ============================================================
__global__ void reduce_kernel(int nblk) {
    const int p = blockIdx.x;
    float s = 0.f;
    for (int i = threadIdx.x; i < nblk; i += 256)
        s += g_partial[(size_t)p * nblk + i];
    #pragma unroll
    for (int m = 1; m < 32; m <<= 1) s += __shfl_xor_sync(0xffffffffu, s, m);
    __shared__ float ws[8];
    if ((threadIdx.x & 31) == 0) ws[threadIdx.x >> 5] = s;
    __syncthreads();
    if (threadIdx.x == 0) {
        float t = 0.f;
        #pragma unroll
        for (int i = 0; i < 8; i++) t += ws[i];
        g_rcp[p] = 1.0f / t;
    }
}

// ============================================================
// pass2: scale s -> weights (in place), transpose via smem, x_out = w^T * x
// ============================================================
__global__ __launch_bounds__(256)
void pass2_kernel(const float* __restrict__ x, float* __restrict__ w,
                  float* __restrict__ x_out, int Ninst) {
    extern __shared__ float tile[];  // [128][129]
    const int n0 = blockIdx.x * 128;
    const int p0 = blockIdx.y * 128;
    const int tx = threadIdx.x & 31, ty = threadIdx.x >> 5;

    #pragma unroll
    for (int i = 0; i < 16; i++) {
        const int pl = i * 8 + ty;
        const float r = g_rcp[p0 + pl];
        float4* wp = (float4*)(w + (size_t)(p0 + pl) * Ninst + n0) + tx;
        float4 v = *wp;
        v.x *= r; v.y *= r; v.z *= r; v.w *= r;
        *wp = v;
        float* t = tile + pl * 129 + tx * 4;
        t[0] = v.x; t[1] = v.y; t[2] = v.z; t[3] = v.w;
    }
    __syncthreads();
    #pragma unroll
    for (int pp = 0; pp < 4; pp++) {
        const int pl = pp * 32 + tx;
        #pragma unroll
        for (int i = 0; i < 16; i++) {
            const int nl = i * 8 + ty;
            const size_t idx = (size_t)(n0 + nl) * C + p0 + pl;
            x_out[idx] = x[idx] * tile[pl * 129 + nl];
        }
    }
}

// ============================================================
// launch
// ============================================================
extern "C" void kernel_launch(void* const* d_in, const int* in_sizes, int n_in,
                              void* d_out, int out_size) {
    const float* x     = (const float*)d_in[0];
    const float* proto = (const float*)d_in[1];
    const int Ninst = in_sizes[0] / C;            // 65536
    float* x_out   = (float*)d_out;               // (N, C)
    float* weights = x_out + (size_t)Ninst * C;   // (P, N)
    const int nblk = Ninst / TILE_M;              // 512

    cudaFuncSetAttribute(pass1_kernel, cudaFuncAttributeMaxDynamicSharedMemorySize,
                         (int)SMEM1_BYTES);
    cudaFuncSetAttribute(pass2_kernel, cudaFuncAttributeMaxDynamicSharedMemorySize,
                         128 * 129 * 4);

    prep_kernel<<<P, 128>>>(proto);
    convert_kernel<<<Ninst, 128>>>(x);
    dummy_kernel<<<1, 32>>>();   // shifts ncu capture slot onto pass1
    pass1_kernel<<<dim3(nblk, P / TILE_P), 256, SMEM1_BYTES>>>(weights, Ninst);
    reduce_kernel<<<P, 256>>>(nblk);
    pass2_kernel<<<dim3(Ninst / 128, P / 128), 256, 128 * 129 * 4>>>(x, weights, x_out, Ninst);
}

// round 7
// speedup vs baseline: 1.2765x; 1.1299x over previous
#include <cuda_runtime.h>
#include <cuda_bf16.h>
#include <cstdint>
#include <cstddef>

#define DINL __device__ __forceinline__

// ---------------- problem constants ----------------
constexpr int C = 512;           // feature dim
constexpr int P = 512;           // prototypes
constexpr int N_MAX = 65536;     // instances
constexpr int TILE_M = 128;      // instances per CTA (pass1)
constexpr int TILE_P = 256;      // protos per CTA (pass1)
constexpr int KC = 64;           // K chunk
constexpr int NCHUNKS = C / KC;  // 8
constexpr int SKB = 144;         // padded smem row stride in BYTES (64 bf16 + 8 pad)
constexpr int MAX_BLOCKS = 1024;

// ---------------- device scratch (static — no allocations) ----------------
__device__ __align__(16) __nv_bfloat16 g_proto_bf[P * C];
__device__ __align__(16) __nv_bfloat16 g_xbf[(size_t)N_MAX * C];
__device__ float g_psq[P];
__device__ float g_xsq[N_MAX];
__device__ float g_partial[(size_t)P * MAX_BLOCKS];
__device__ float g_rcp[P];

// ---------------- PTX helpers ----------------
DINL uint32_t smem_u32(const void* p) {
    uint32_t r;
    asm("{ .reg .u64 t; cvta.to.shared.u64 t, %1; cvt.u32.u64 %0, t; }"
        : "=r"(r) : "l"(p));
    return r;
}

#define CP_ASYNC16(dst, src) \
    asm volatile("cp.async.cg.shared.global [%0], [%1], 16;" \
                 :: "r"(dst), "l"(src) : "memory")
#define CP_COMMIT() asm volatile("cp.async.commit_group;" ::: "memory")
#define CP_WAIT(n)  asm volatile("cp.async.wait_group %0;" :: "n"(n) : "memory")

#define LDSM_X4(r0, r1, r2, r3, addr) \
    asm volatile("ldmatrix.sync.aligned.m8n8.x4.shared.b16 {%0,%1,%2,%3}, [%4];" \
                 : "=r"(r0), "=r"(r1), "=r"(r2), "=r"(r3) : "r"(addr))
#define LDSM_X2(r0, r1, addr) \
    asm volatile("ldmatrix.sync.aligned.m8n8.x2.shared.b16 {%0,%1}, [%2];" \
                 : "=r"(r0), "=r"(r1) : "r"(addr))

#define MMA_BF16(c, a, b0, b1) \
    asm volatile("mma.sync.aligned.m16n8k16.row.col.f32.bf16.bf16.f32 " \
                 "{%0,%1,%2,%3}, {%4,%5,%6,%7}, {%8,%9}, {%0,%1,%2,%3};" \
                 : "+f"((c)[0]), "+f"((c)[1]), "+f"((c)[2]), "+f"((c)[3]) \
                 : "r"((a)[0]), "r"((a)[1]), "r"((a)[2]), "r"((a)[3]), \
                   "r"(b0), "r"(b1))

DINL uint32_t bf2_bits(__nv_bfloat162 v) { return *reinterpret_cast<uint32_t*>(&v); }

// ---------------- pass1 SMEM layout (bytes) ----------------
constexpr uint32_t SM_XSQ  = 0;                            // 128 f
constexpr uint32_t SM_PSQ  = 512;                          // 256 f
constexpr uint32_t SM_SUMS = 1536;                         // 2 x 256 f
constexpr uint32_t SM_A0   = 4096;                         // 128 x 144B
constexpr uint32_t SM_A1   = SM_A0 + TILE_M * SKB;         // 22528
constexpr uint32_t SM_B0   = SM_A1 + TILE_M * SKB;         // 40960: 256 x 144B
constexpr uint32_t SM_B1   = SM_B0 + TILE_P * SKB;         // 77824
constexpr uint32_t SMEM1_BYTES = SM_B1 + TILE_P * SKB;     // 114688

// ============================================================
// prep: proto fp32 -> bf16 + ||p||^2
// ============================================================
__global__ void prep_kernel(const float* __restrict__ proto) {
    const int p = blockIdx.x;
    const int t = threadIdx.x;  // 128 threads
    float4 v = ((const float4*)(proto + (size_t)p * C))[t];
    __nv_bfloat162 b0 = __float22bfloat162_rn(make_float2(v.x, v.y));
    __nv_bfloat162 b1 = __float22bfloat162_rn(make_float2(v.z, v.w));
    *(uint2*)(g_proto_bf + (size_t)p * C + t * 4) = make_uint2(bf2_bits(b0), bf2_bits(b1));
    float sq = v.x * v.x + v.y * v.y + v.z * v.z + v.w * v.w;
    #pragma unroll
    for (int m = 1; m < 32; m <<= 1) sq += __shfl_xor_sync(0xffffffffu, sq, m);
    __shared__ float ws[4];
    if ((t & 31) == 0) ws[t >> 5] = sq;
    __syncthreads();
    if (t == 0) g_psq[p] = ws[0] + ws[1] + ws[2] + ws[3];
}

// ============================================================
// convert: x fp32 -> bf16 + ||x||^2 per instance
// ============================================================
__global__ void convert_kernel(const float* __restrict__ x) {
    const int row = blockIdx.x;
    const int t = threadIdx.x;  // 128 threads
    float4 v = ((const float4*)(x + (size_t)row * C))[t];
    __nv_bfloat162 b0 = __float22bfloat162_rn(make_float2(v.x, v.y));
    __nv_bfloat162 b1 = __float22bfloat162_rn(make_float2(v.z, v.w));
    *(uint2*)(g_xbf + (size_t)row * C + t * 4) = make_uint2(bf2_bits(b0), bf2_bits(b1));
    float sq = v.x * v.x + v.y * v.y + v.z * v.z + v.w * v.w;
    #pragma unroll
    for (int m = 1; m < 32; m <<= 1) sq += __shfl_xor_sync(0xffffffffu, sq, m);
    __shared__ float ws[4];
    if ((t & 31) == 0) ws[t >> 5] = sq;
    __syncthreads();
    if (t == 0) g_xsq[row] = ws[0] + ws[1] + ws[2] + ws[3];
}

// ============================================================
// dummy: shifts the ncu capture slot so pass1 lands on it
// ============================================================
__global__ void dummy_kernel() {}

// ============================================================
// pass1: bf16 mma.sync GEMM tile (128 inst x 256 protos, K=512)
//        512 threads / 16 warps (warp tile 64x32) for 4 warps/SMSP
// ============================================================
__global__ __launch_bounds__(512, 1)
void pass1_kernel(float* __restrict__ w_s, int Ninst) {
    extern __shared__ char smem[];
    const uint32_t sb = smem_u32(smem);
    const int tid  = threadIdx.x;
    const int wid  = tid >> 5;
    const int l    = tid & 31;
    const int mw   = wid >> 3;   // 0..1 : 64-row half
    const int nw   = wid & 7;    // 0..7 : 32-proto slice
    const int n0   = blockIdx.x * TILE_M;
    const int p0   = blockIdx.y * TILE_P;

    // stage xsq / psq
    if (tid < 128) ((float*)(smem + SM_XSQ))[tid] = g_xsq[n0 + tid];
    if (tid < 256) ((float*)(smem + SM_PSQ))[tid] = g_psq[p0 + tid];

    // per-thread cp.async mapping (512 threads):
    // A: 1024 16B segs (128 rows x 8) -> 2/thread ; B: 2048 segs -> 4/thread
    const int rA = tid >> 3;         // 0..63
    const int sA = tid & 7;
    const __nv_bfloat16* aS0 = g_xbf + (size_t)(n0 + rA) * C + sA * 8;
    const uint32_t aD0 = sb + SM_A0 + rA * SKB + sA * 16;
    const __nv_bfloat16* bS0 = g_proto_bf + (size_t)(p0 + rA) * C + sA * 8;
    const uint32_t bD0 = sb + SM_B0 + rA * SKB + sA * 16;
    const uint32_t bufStrideA = SM_A1 - SM_A0;
    const uint32_t bufStrideB = SM_B1 - SM_B0;

    #define ISSUE_CHUNK(ck, buf) do {                                           \
        const uint32_t _ao = (buf) * bufStrideA + (ck) * 0;                      \
        const uint32_t _bo = (buf) * bufStrideB;                                 \
        CP_ASYNC16(aD0 + _ao,                 aS0 + (ck) * KC);                  \
        CP_ASYNC16(aD0 + _ao + 64 * SKB,      aS0 + (ck) * KC + 64 * C);         \
        _Pragma("unroll")                                                        \
        for (int q = 0; q < 4; q++)                                              \
            CP_ASYNC16(bD0 + _bo + q * 64 * SKB, bS0 + (ck) * KC + q * 64 * C);  \
        CP_COMMIT();                                                             \
    } while (0)

    ISSUE_CHUNK(0, 0);
    ISSUE_CHUNK(1, 1);

    // fragment lane offsets
    const uint32_t aRowOff = (mw * 64 + (l & 15)) * SKB + (l >> 4) * 16;
    const uint32_t bRowOff = (nw * 32 + (l & 7)) * SKB + ((l >> 3) & 1) * 16;

    float c[4][4][4];
    #pragma unroll
    for (int im = 0; im < 4; im++)
        #pragma unroll
        for (int in = 0; in < 4; in++)
            #pragma unroll
            for (int r = 0; r < 4; r++) c[im][in][r] = 0.f;

    #pragma unroll 1
    for (int ck = 0; ck < NCHUNKS; ck++) {
        if (ck >= NCHUNKS - 2) { CP_WAIT(0); } else { CP_WAIT(1); }
        __syncthreads();
        const int buf = ck & 1;
        const uint32_t Ab = sb + (buf ? SM_A1 : SM_A0) + aRowOff;
        const uint32_t Bb = sb + (buf ? SM_B1 : SM_B0) + bRowOff;
        #pragma unroll
        for (int ks = 0; ks < 4; ks++) {
            uint32_t a[4][4];
            #pragma unroll
            for (int im = 0; im < 4; im++)
                LDSM_X4(a[im][0], a[im][1], a[im][2], a[im][3],
                        Ab + im * 16 * SKB + ks * 32);
            #pragma unroll
            for (int in = 0; in < 4; in++) {
                uint32_t b0, b1;
                LDSM_X2(b0, b1, Bb + in * 8 * SKB + ks * 32);
                #pragma unroll
                for (int im = 0; im < 4; im++)
                    MMA_BF16(c[im][in], a[im], b0, b1);
            }
        }
        __syncthreads();
        if (ck + 2 < NCHUNKS) ISSUE_CHUNK(ck + 2, buf);
    }

    // ---------------- epilogue (direct stores: 4 full 32B sectors / warp op) --
    const float* xsq_s = (const float*)(smem + SM_XSQ);
    const float* psq_s = (const float*)(smem + SM_PSQ);
    float* sums = (float*)(smem + SM_SUMS);

    float csum[4][2];
    #pragma unroll
    for (int in = 0; in < 4; in++) { csum[in][0] = 0.f; csum[in][1] = 0.f; }

    #pragma unroll
    for (int im = 0; im < 4; im++) {
        const int rbase = mw * 64 + im * 16 + (l >> 2);
        #pragma unroll
        for (int rh = 0; rh < 2; rh++) {
            const int row = rbase + rh * 8;
            const float xq = xsq_s[row];
            const size_t gcol = (size_t)(n0 + row);
            #pragma unroll
            for (int in = 0; in < 4; in++) {
                const int pl = nw * 32 + in * 8 + (l & 3) * 2;
                #pragma unroll
                for (int cj = 0; cj < 2; cj++) {
                    const float acc = c[im][in][rh * 2 + cj];
                    float d2 = fmaxf(fmaf(-2.f, acc, psq_s[pl + cj] + xq), 1e-20f);
                    float s = rsqrtf(d2);
                    w_s[(size_t)(p0 + pl + cj) * Ninst + gcol] = s;
                    csum[in][cj] += s;
                }
            }
        }
    }
    // reduce column sums over lanes sharing (l&3)
    #pragma unroll
    for (int in = 0; in < 4; in++) {
        #pragma unroll
        for (int cj = 0; cj < 2; cj++) {
            float v = csum[in][cj];
            v += __shfl_xor_sync(0xffffffffu, v, 4);
            v += __shfl_xor_sync(0xffffffffu, v, 8);
            v += __shfl_xor_sync(0xffffffffu, v, 16);
            if (l < 4) sums[mw * 256 + nw * 32 + in * 8 + l * 2 + cj] = v;
        }
    }
    __syncthreads();
    if (tid < 256) {
        float tot = sums[tid] + sums[256 + tid];
        g_partial[(size_t)(p0 + tid) * gridDim.x + blockIdx.x] = tot;
    }
}

// ============================================================
// reduce: fixed-order tree over per-CTA partials -> g_rcp[p] = 1/sum
// ============================================================
__global__ void reduce_kernel(int nblk) {
    const int p = blockIdx.x;
    float s = 0.f;
    for (int i = threadIdx.x; i < nblk; i += 256)
        s += g_partial[(size_t)p * nblk + i];
    #pragma unroll
    for (int m = 1; m < 32; m <<= 1) s += __shfl_xor_sync(0xffffffffu, s, m);
    __shared__ float ws[8];
    if ((threadIdx.x & 31) == 0) ws[threadIdx.x >> 5] = s;
    __syncthreads();
    if (threadIdx.x == 0) {
        float t = 0.f;
        #pragma unroll
        for (int i = 0; i < 8; i++) t += ws[i];
        g_rcp[p] = 1.0f / t;
    }
}

// ============================================================
// pass2: scale s -> weights (in place), transpose via smem, x_out = w^T * x
// ============================================================
__global__ __launch_bounds__(256)
void pass2_kernel(const float* __restrict__ x, float* __restrict__ w,
                  float* __restrict__ x_out, int Ninst) {
    extern __shared__ float tile[];  // [128][129]
    const int n0 = blockIdx.x * 128;
    const int p0 = blockIdx.y * 128;
    const int tx = threadIdx.x & 31, ty = threadIdx.x >> 5;

    #pragma unroll
    for (int i = 0; i < 16; i++) {
        const int pl = i * 8 + ty;
        const float r = g_rcp[p0 + pl];
        float4* wp = (float4*)(w + (size_t)(p0 + pl) * Ninst + n0) + tx;
        float4 v = *wp;
        v.x *= r; v.y *= r; v.z *= r; v.w *= r;
        *wp = v;
        float* t = tile + pl * 129 + tx * 4;
        t[0] = v.x; t[1] = v.y; t[2] = v.z; t[3] = v.w;
    }
    __syncthreads();
    #pragma unroll
    for (int pp = 0; pp < 4; pp++) {
        const int pl = pp * 32 + tx;
        #pragma unroll
        for (int i = 0; i < 16; i++) {
            const int nl = i * 8 + ty;
            const size_t idx = (size_t)(n0 + nl) * C + p0 + pl;
            x_out[idx] = x[idx] * tile[pl * 129 + nl];
        }
    }
}

// ============================================================
// launch
// ============================================================
extern "C" void kernel_launch(void* const* d_in, const int* in_sizes, int n_in,
                              void* d_out, int out_size) {
    const float* x     = (const float*)d_in[0];
    const float* proto = (const float*)d_in[1];
    const int Ninst = in_sizes[0] / C;            // 65536
    float* x_out   = (float*)d_out;               // (N, C)
    float* weights = x_out + (size_t)Ninst * C;   // (P, N)
    const int nblk = Ninst / TILE_M;              // 512

    cudaFuncSetAttribute(pass1_kernel, cudaFuncAttributeMaxDynamicSharedMemorySize,
                         (int)SMEM1_BYTES);
    cudaFuncSetAttribute(pass2_kernel, cudaFuncAttributeMaxDynamicSharedMemorySize,
                         128 * 129 * 4);

    prep_kernel<<<P, 128>>>(proto);
    convert_kernel<<<Ninst, 128>>>(x);
    dummy_kernel<<<1, 32>>>();   // keeps ncu capture slot on pass1
    pass1_kernel<<<dim3(nblk, P / TILE_P), 512, SMEM1_BYTES>>>(weights, Ninst);
    reduce_kernel<<<P, 256>>>(nblk);
    pass2_kernel<<<dim3(Ninst / 128, P / 128), 256, 128 * 129 * 4>>>(x, weights, x_out, Ninst);
}

// round 8
// speedup vs baseline: 1.2889x; 1.0097x over previous
#include <cuda_runtime.h>
#include <cuda_bf16.h>
#include <cstdint>
#include <cstddef>

#define DINL __device__ __forceinline__

// ---------------- problem constants ----------------
constexpr int C = 512;           // feature dim
constexpr int P = 512;           // prototypes
constexpr int N_MAX = 65536;     // instances
constexpr int TILE_M = 128;      // instances per CTA (pass1)
constexpr int TILE_P = 256;      // protos per CTA (pass1)
constexpr int KC = 64;           // K chunk
constexpr int NCHUNKS = C / KC;  // 8
constexpr int SKB = 144;         // padded smem row stride in BYTES (64 bf16 + 8 pad)
constexpr int MAX_BLOCKS = 1024;

// ---------------- device scratch (static — no allocations) ----------------
__device__ __align__(16) __nv_bfloat16 g_proto_bf[P * C];
__device__ __align__(16) __nv_bfloat16 g_xbf[(size_t)N_MAX * C];
__device__ float g_psq[P];
__device__ float g_xsq[N_MAX];
__device__ float g_partial[(size_t)P * MAX_BLOCKS];
__device__ float g_rcp[P];

// ---------------- PTX helpers ----------------
DINL uint32_t smem_u32(const void* p) {
    uint32_t r;
    asm("{ .reg .u64 t; cvta.to.shared.u64 t, %1; cvt.u32.u64 %0, t; }"
        : "=r"(r) : "l"(p));
    return r;
}

#define CP_ASYNC16(dst, src) \
    asm volatile("cp.async.cg.shared.global [%0], [%1], 16;" \
                 :: "r"(dst), "l"(src) : "memory")
#define CP_COMMIT() asm volatile("cp.async.commit_group;" ::: "memory")
#define CP_WAIT(n)  asm volatile("cp.async.wait_group %0;" :: "n"(n) : "memory")

#define LDSM_X4(r0, r1, r2, r3, addr) \
    asm volatile("ldmatrix.sync.aligned.m8n8.x4.shared.b16 {%0,%1,%2,%3}, [%4];" \
                 : "=r"(r0), "=r"(r1), "=r"(r2), "=r"(r3) : "r"(addr))
#define LDSM_X2(r0, r1, addr) \
    asm volatile("ldmatrix.sync.aligned.m8n8.x2.shared.b16 {%0,%1}, [%2];" \
                 : "=r"(r0), "=r"(r1) : "r"(addr))

#define MMA_BF16(c, a, b0, b1) \
    asm volatile("mma.sync.aligned.m16n8k16.row.col.f32.bf16.bf16.f32 " \
                 "{%0,%1,%2,%3}, {%4,%5,%6,%7}, {%8,%9}, {%0,%1,%2,%3};" \
                 : "+f"((c)[0]), "+f"((c)[1]), "+f"((c)[2]), "+f"((c)[3]) \
                 : "r"((a)[0]), "r"((a)[1]), "r"((a)[2]), "r"((a)[3]), \
                   "r"(b0), "r"(b1))

DINL uint32_t bf2_bits(__nv_bfloat162 v) { return *reinterpret_cast<uint32_t*>(&v); }

// ---------------- pass1 SMEM layout (bytes) ----------------
constexpr uint32_t SM_XSQ  = 0;                            // 128 f
constexpr uint32_t SM_PSQ  = 512;                          // 256 f
constexpr uint32_t SM_SUMS = 1536;                         // 2 x 256 f
constexpr uint32_t SM_A0   = 4096;                         // 128 x 144B
constexpr uint32_t SM_A1   = SM_A0 + TILE_M * SKB;         // 22528
constexpr uint32_t SM_B0   = SM_A1 + TILE_M * SKB;         // 40960: 256 x 144B
constexpr uint32_t SM_B1   = SM_B0 + TILE_P * SKB;         // 77824
constexpr uint32_t SMEM1_BYTES = SM_B1 + TILE_P * SKB;     // 114688

// ============================================================
// prep: proto fp32 -> bf16 + ||p||^2
// ============================================================
__global__ void prep_kernel(const float* __restrict__ proto) {
    const int p = blockIdx.x;
    const int t = threadIdx.x;  // 128 threads
    float4 v = ((const float4*)(proto + (size_t)p * C))[t];
    __nv_bfloat162 b0 = __float22bfloat162_rn(make_float2(v.x, v.y));
    __nv_bfloat162 b1 = __float22bfloat162_rn(make_float2(v.z, v.w));
    *(uint2*)(g_proto_bf + (size_t)p * C + t * 4) = make_uint2(bf2_bits(b0), bf2_bits(b1));
    float sq = v.x * v.x + v.y * v.y + v.z * v.z + v.w * v.w;
    #pragma unroll
    for (int m = 1; m < 32; m <<= 1) sq += __shfl_xor_sync(0xffffffffu, sq, m);
    __shared__ float ws[4];
    if ((t & 31) == 0) ws[t >> 5] = sq;
    __syncthreads();
    if (t == 0) g_psq[p] = ws[0] + ws[1] + ws[2] + ws[3];
}

// ============================================================
// convert: x fp32 -> bf16 + ||x||^2 per instance
// ============================================================
__global__ void convert_kernel(const float* __restrict__ x) {
    const int row = blockIdx.x;
    const int t = threadIdx.x;  // 128 threads
    float4 v = ((const float4*)(x + (size_t)row * C))[t];
    __nv_bfloat162 b0 = __float22bfloat162_rn(make_float2(v.x, v.y));
    __nv_bfloat162 b1 = __float22bfloat162_rn(make_float2(v.z, v.w));
    *(uint2*)(g_xbf + (size_t)row * C + t * 4) = make_uint2(bf2_bits(b0), bf2_bits(b1));
    float sq = v.x * v.x + v.y * v.y + v.z * v.z + v.w * v.w;
    #pragma unroll
    for (int m = 1; m < 32; m <<= 1) sq += __shfl_xor_sync(0xffffffffu, sq, m);
    __shared__ float ws[4];
    if ((t & 31) == 0) ws[t >> 5] = sq;
    __syncthreads();
    if (t == 0) g_xsq[row] = ws[0] + ws[1] + ws[2] + ws[3];
}

// ============================================================
// dummy: shifts the ncu capture slot so pass1 lands on it
// ============================================================
__global__ void dummy_kernel() {}

// ============================================================
// pass1: bf16 mma.sync GEMM tile (128 inst x 256 protos, K=512)
//        512 threads / 16 warps (warp tile 64x32) for 4 warps/SMSP
// ============================================================
__global__ __launch_bounds__(512, 1)
void pass1_kernel(float* __restrict__ w_s, int Ninst) {
    extern __shared__ char smem[];
    const uint32_t sb = smem_u32(smem);
    const int tid  = threadIdx.x;
    const int wid  = tid >> 5;
    const int l    = tid & 31;
    const int mw   = wid >> 3;   // 0..1 : 64-row half
    const int nw   = wid & 7;    // 0..7 : 32-proto slice
    const int n0   = blockIdx.x * TILE_M;
    const int p0   = blockIdx.y * TILE_P;

    // stage xsq / psq
    if (tid < 128) ((float*)(smem + SM_XSQ))[tid] = g_xsq[n0 + tid];
    if (tid < 256) ((float*)(smem + SM_PSQ))[tid] = g_psq[p0 + tid];

    // per-thread cp.async mapping (512 threads):
    // A: 1024 16B segs (128 rows x 8) -> 2/thread ; B: 2048 segs -> 4/thread
    const int rA = tid >> 3;         // 0..63
    const int sA = tid & 7;
    const __nv_bfloat16* aS0 = g_xbf + (size_t)(n0 + rA) * C + sA * 8;
    const uint32_t aD0 = sb + SM_A0 + rA * SKB + sA * 16;
    const __nv_bfloat16* bS0 = g_proto_bf + (size_t)(p0 + rA) * C + sA * 8;
    const uint32_t bD0 = sb + SM_B0 + rA * SKB + sA * 16;
    const uint32_t bufStrideA = SM_A1 - SM_A0;
    const uint32_t bufStrideB = SM_B1 - SM_B0;

    #define ISSUE_CHUNK(ck, buf) do {                                           \
        const uint32_t _ao = (buf) * bufStrideA + (ck) * 0;                      \
        const uint32_t _bo = (buf) * bufStrideB;                                 \
        CP_ASYNC16(aD0 + _ao,                 aS0 + (ck) * KC);                  \
        CP_ASYNC16(aD0 + _ao + 64 * SKB,      aS0 + (ck) * KC + 64 * C);         \
        _Pragma("unroll")                                                        \
        for (int q = 0; q < 4; q++)                                              \
            CP_ASYNC16(bD0 + _bo + q * 64 * SKB, bS0 + (ck) * KC + q * 64 * C);  \
        CP_COMMIT();                                                             \
    } while (0)

    ISSUE_CHUNK(0, 0);
    ISSUE_CHUNK(1, 1);

    // fragment lane offsets
    const uint32_t aRowOff = (mw * 64 + (l & 15)) * SKB + (l >> 4) * 16;
    const uint32_t bRowOff = (nw * 32 + (l & 7)) * SKB + ((l >> 3) & 1) * 16;

    float c[4][4][4];
    #pragma unroll
    for (int im = 0; im < 4; im++)
        #pragma unroll
        for (int in = 0; in < 4; in++)
            #pragma unroll
            for (int r = 0; r < 4; r++) c[im][in][r] = 0.f;

    #pragma unroll 1
    for (int ck = 0; ck < NCHUNKS; ck++) {
        if (ck >= NCHUNKS - 2) { CP_WAIT(0); } else { CP_WAIT(1); }
        __syncthreads();
        const int buf = ck & 1;
        const uint32_t Ab = sb + (buf ? SM_A1 : SM_A0) + aRowOff;
        const uint32_t Bb = sb + (buf ? SM_B1 : SM_B0) + bRowOff;
        #pragma unroll
        for (int ks = 0; ks < 4; ks++) {
            uint32_t a[4][4];
            #pragma unroll
            for (int im = 0; im < 4; im++)
                LDSM_X4(a[im][0], a[im][1], a[im][2], a[im][3],
                        Ab + im * 16 * SKB + ks * 32);
            #pragma unroll
            for (int in = 0; in < 4; in++) {
                uint32_t b0, b1;
                LDSM_X2(b0, b1, Bb + in * 8 * SKB + ks * 32);
                #pragma unroll
                for (int im = 0; im < 4; im++)
                    MMA_BF16(c[im][in], a[im], b0, b1);
            }
        }
        __syncthreads();
        if (ck + 2 < NCHUNKS) ISSUE_CHUNK(ck + 2, buf);
    }

    // ---------------- epilogue (direct stores: 4 full 32B sectors / warp op) --
    const float* xsq_s = (const float*)(smem + SM_XSQ);
    const float* psq_s = (const float*)(smem + SM_PSQ);
    float* sums = (float*)(smem + SM_SUMS);

    float csum[4][2];
    #pragma unroll
    for (int in = 0; in < 4; in++) { csum[in][0] = 0.f; csum[in][1] = 0.f; }

    #pragma unroll
    for (int im = 0; im < 4; im++) {
        const int rbase = mw * 64 + im * 16 + (l >> 2);
        #pragma unroll
        for (int rh = 0; rh < 2; rh++) {
            const int row = rbase + rh * 8;
            const float xq = xsq_s[row];
            const size_t gcol = (size_t)(n0 + row);
            #pragma unroll
            for (int in = 0; in < 4; in++) {
                const int pl = nw * 32 + in * 8 + (l & 3) * 2;
                #pragma unroll
                for (int cj = 0; cj < 2; cj++) {
                    const float acc = c[im][in][rh * 2 + cj];
                    float d2 = fmaxf(fmaf(-2.f, acc, psq_s[pl + cj] + xq), 1e-20f);
                    float s = rsqrtf(d2);
                    w_s[(size_t)(p0 + pl + cj) * Ninst + gcol] = s;
                    csum[in][cj] += s;
                }
            }
        }
    }
    // reduce column sums over lanes sharing (l&3)
    #pragma unroll
    for (int in = 0; in < 4; in++) {
        #pragma unroll
        for (int cj = 0; cj < 2; cj++) {
            float v = csum[in][cj];
            v += __shfl_xor_sync(0xffffffffu, v, 4);
            v += __shfl_xor_sync(0xffffffffu, v, 8);
            v += __shfl_xor_sync(0xffffffffu, v, 16);
            if (l < 4) sums[mw * 256 + nw * 32 + in * 8 + l * 2 + cj] = v;
        }
    }
    __syncthreads();
    if (tid < 256) {
        float tot = sums[tid] + sums[256 + tid];
        g_partial[(size_t)(p0 + tid) * gridDim.x + blockIdx.x] = tot;
    }
}

// ============================================================
// reduce: fixed-order tree over per-CTA partials -> g_rcp[p] = 1/sum
// ============================================================
__global__ void reduce_kernel(int nblk) {
    const int p = blockIdx.x;
    float s = 0.f;
    for (int i = threadIdx.x; i < nblk; i += 256)
        s += g_partial[(size_t)p * nblk + i];
    #pragma unroll
    for (int m = 1; m < 32; m <<= 1) s += __shfl_xor_sync(0xffffffffu, s, m);
    __shared__ float ws[8];
    if ((threadIdx.x & 31) == 0) ws[threadIdx.x >> 5] = s;
    __syncthreads();
    if (threadIdx.x == 0) {
        float t = 0.f;
        #pragma unroll
        for (int i = 0; i < 8; i++) t += ws[i];
        g_rcp[p] = 1.0f / t;
    }
}

// ============================================================
// pass2: scale s -> weights (in place), transpose via smem, x_out = w^T * x
// ============================================================
__global__ __launch_bounds__(256)
void pass2_kernel(const float* __restrict__ x, float* __restrict__ w,
                  float* __restrict__ x_out, int Ninst) {
    extern __shared__ float tile[];  // [128][129]
    const int n0 = blockIdx.x * 128;
    const int p0 = blockIdx.y * 128;
    const int tx = threadIdx.x & 31, ty = threadIdx.x >> 5;

    #pragma unroll
    for (int i = 0; i < 16; i++) {
        const int pl = i * 8 + ty;
        const float r = g_rcp[p0 + pl];
        float4* wp = (float4*)(w + (size_t)(p0 + pl) * Ninst + n0) + tx;
        float4 v = *wp;
        v.x *= r; v.y *= r; v.z *= r; v.w *= r;
        *wp = v;
        float* t = tile + pl * 129 + tx * 4;
        t[0] = v.x; t[1] = v.y; t[2] = v.z; t[3] = v.w;
    }
    __syncthreads();
    #pragma unroll
    for (int pp = 0; pp < 4; pp++) {
        const int pl = pp * 32 + tx;
        #pragma unroll
        for (int i = 0; i < 16; i++) {
            const int nl = i * 8 + ty;
            const size_t idx = (size_t)(n0 + nl) * C + p0 + pl;
            x_out[idx] = x[idx] * tile[pl * 129 + nl];
        }
    }
}

// ============================================================
// launch
// ============================================================
extern "C" void kernel_launch(void* const* d_in, const int* in_sizes, int n_in,
                              void* d_out, int out_size) {
    const float* x     = (const float*)d_in[0];
    const float* proto = (const float*)d_in[1];
    const int Ninst = in_sizes[0] / C;            // 65536
    float* x_out   = (float*)d_out;               // (N, C)
    float* weights = x_out + (size_t)Ninst * C;   // (P, N)
    const int nblk = Ninst / TILE_M;              // 512

    cudaFuncSetAttribute(pass1_kernel, cudaFuncAttributeMaxDynamicSharedMemorySize,
                         (int)SMEM1_BYTES);
    cudaFuncSetAttribute(pass2_kernel, cudaFuncAttributeMaxDynamicSharedMemorySize,
                         128 * 129 * 4);

    prep_kernel<<<P, 128>>>(proto);
    convert_kernel<<<Ninst, 128>>>(x);
    dummy_kernel<<<1, 32>>>();   // keeps ncu capture slot on pass1
    pass1_kernel<<<dim3(nblk, P / TILE_P), 512, SMEM1_BYTES>>>(weights, Ninst);
    reduce_kernel<<<P, 256>>>(nblk);
    pass2_kernel<<<dim3(Ninst / 128, P / 128), 256, 128 * 129 * 4>>>(x, weights, x_out, Ninst);
}